// round 7
// baseline (speedup 1.0000x reference)
#include <cuda_runtime.h>
#include <cstdint>
#include <math.h>

#define B_  4
#define N_  2048
#define D_  1024
#define H_  16
#define DH_ 64

// Scratch: projected Q/K/V in [B*H][N][dh] layout, attention output X in [B*N][D]
__device__ float g_Q[B_ * H_ * N_ * DH_];
__device__ float g_K[B_ * H_ * N_ * DH_];
__device__ float g_V[B_ * H_ * N_ * DH_];
__device__ float g_X[B_ * N_ * D_];

__device__ __forceinline__ uint32_t f2tf32(float x) {
    uint32_t r;
    asm("cvt.rna.tf32.f32 %0, %1;" : "=r"(r) : "f"(x));
    return r;
}
__device__ __forceinline__ float ex2f(float x) {
    float y;
    asm("ex2.approx.ftz.f32 %0, %1;" : "=f"(y) : "f"(x));
    return y;
}

__device__ __forceinline__ void mma_tf32_16x8x8(
    float& c0, float& c1, float& c2, float& c3,
    uint32_t a0, uint32_t a1, uint32_t a2, uint32_t a3,
    uint32_t b0, uint32_t b1)
{
    asm volatile(
        "mma.sync.aligned.m16n8k8.row.col.f32.tf32.tf32.f32 "
        "{%0,%1,%2,%3}, {%4,%5,%6,%7}, {%8,%9}, {%0,%1,%2,%3};"
        : "+f"(c0), "+f"(c1), "+f"(c2), "+f"(c3)
        : "r"(a0), "r"(a1), "r"(a2), "r"(a3), "r"(b0), "r"(b1));
}

// ===========================================================================
// tf32 mma.sync GEMM: C[M,1024] = A[M,1024] @ W^T (+bias), W row-major [N][K].
// CTA tile 128x128, k-tile 32, 8 warps (4m x 2n), warp tile 32x64.
// Smem: 128 rows x 32 floats, 16B-chunk XOR swizzle (conflict-free STS+LDS).
// Register-prefetch double buffer: LDG tile t+1 -> regs, compute t, STS t+1.
// One __syncthreads per k-tile.
// ===========================================================================
#define MAT_FLOATS (128 * 32)              // 16 KB per matrix tile
#define STAGE_FLOATS (2 * MAT_FLOATS)      // A + B
#define GEMM_SMEM (2 * STAGE_FLOATS * 4)   // 2 stages = 64 KB

__device__ __forceinline__ int swz_slot(int row, int chunk) {
    return row * 8 + (chunk ^ (row & 7));  // 16B-chunk index
}

template <bool OUT_HEADS, bool HAS_BIAS>
__device__ __forceinline__ void gemm_mma_body(
    const float* __restrict__ A, const float* __restrict__ W,
    const float* __restrict__ bias, float* __restrict__ out)
{
    extern __shared__ float gsm[];

    const int tid  = threadIdx.x;
    const int wid  = tid >> 5;
    const int lane = tid & 31;
    const int g    = lane >> 2;
    const int tig  = lane & 3;
    const int wm   = wid & 3;
    const int wn   = wid >> 2;
    const int m0   = blockIdx.y * 128;
    const int n0   = blockIdx.x * 128;

    const int prow = tid >> 1;               // producer row 0..127
    const int pq   = (tid & 1) * 4;          // producer chunk base {0,4}

    float c[2][8][4];
#pragma unroll
    for (int t = 0; t < 2; t++)
#pragma unroll
        for (int j = 0; j < 8; j++)
#pragma unroll
            for (int e = 0; e < 4; e++) c[t][j][e] = 0.f;

    const float* Ath = A + (size_t)(m0 + prow) * D_ + pq * 4;
    const float* Wth = W + (size_t)(n0 + prow) * D_ + pq * 4;

    float4 pa[4], pw[4];

#pragma unroll
    for (int j = 0; j < 4; j++) {
        pa[j] = __ldg((const float4*)(Ath + j * 4));
        pw[j] = __ldg((const float4*)(Wth + j * 4));
    }
    // store tile 0 into stage 0
    {
        float* As = gsm;
        float* Bs = gsm + MAT_FLOATS;
#pragma unroll
        for (int j = 0; j < 4; j++) {
            int slot = swz_slot(prow, pq + j);
            *(float4*)(As + slot * 4) = pa[j];
            *(float4*)(Bs + slot * 4) = pw[j];
        }
    }
    __syncthreads();

    const int NK = D_ / 32;
    for (int kt = 0; kt < NK; kt++) {
        // prefetch tile kt+1 into registers (latency hidden by compute below)
        if (kt + 1 < NK) {
            const float* Ag = Ath + (kt + 1) * 32;
            const float* Wg = Wth + (kt + 1) * 32;
#pragma unroll
            for (int j = 0; j < 4; j++) {
                pa[j] = __ldg((const float4*)(Ag + j * 4));
                pw[j] = __ldg((const float4*)(Wg + j * 4));
            }
        }

        const float* As = gsm + (kt & 1) * STAGE_FLOATS;
        const float* Bs = As + MAT_FLOATS;

#pragma unroll
        for (int kk = 0; kk < 32; kk += 8) {
            const int ch = kk >> 2;
            uint32_t a[2][4];
#pragma unroll
            for (int t = 0; t < 2; t++) {
                const int r = wm * 32 + t * 16 + g;
                const int x7 = r & 7;
                a[t][0] = f2tf32(As[swz_slot(r,     ch)     * 4 + tig]);
                a[t][1] = f2tf32(As[swz_slot(r + 8, ch)     * 4 + tig]);
                a[t][2] = f2tf32(As[swz_slot(r,     ch + 1) * 4 + tig]);
                a[t][3] = f2tf32(As[swz_slot(r + 8, ch + 1) * 4 + tig]);
                (void)x7;
            }
#pragma unroll
            for (int j = 0; j < 8; j++) {
                const int r = wn * 64 + j * 8 + g;
                uint32_t b0 = f2tf32(Bs[swz_slot(r, ch)     * 4 + tig]);
                uint32_t b1 = f2tf32(Bs[swz_slot(r, ch + 1) * 4 + tig]);
                mma_tf32_16x8x8(c[0][j][0], c[0][j][1], c[0][j][2], c[0][j][3],
                                a[0][0], a[0][1], a[0][2], a[0][3], b0, b1);
                mma_tf32_16x8x8(c[1][j][0], c[1][j][1], c[1][j][2], c[1][j][3],
                                a[1][0], a[1][1], a[1][2], a[1][3], b0, b1);
            }
        }

        if (kt + 1 < NK) {
            float* Ad = gsm + ((kt + 1) & 1) * STAGE_FLOATS;
            float* Bd = Ad + MAT_FLOATS;
#pragma unroll
            for (int j = 0; j < 4; j++) {
                int slot = swz_slot(prow, pq + j);
                *(float4*)(Ad + slot * 4) = pa[j];
                *(float4*)(Bd + slot * 4) = pw[j];
            }
        }
        __syncthreads();
    }

#pragma unroll
    for (int t = 0; t < 2; t++) {
        const int r0 = m0 + wm * 32 + t * 16 + g;
#pragma unroll
        for (int j = 0; j < 8; j++) {
            const int col = n0 + wn * 64 + j * 8 + tig * 2;
            float2 v0 = make_float2(c[t][j][0], c[t][j][1]);
            float2 v1 = make_float2(c[t][j][2], c[t][j][3]);
            if (HAS_BIAS) {
                float2 bv = *(const float2*)(bias + col);
                v0.x += bv.x; v0.y += bv.y;
                v1.x += bv.x; v1.y += bv.y;
            }
            if (OUT_HEADS) {
                const int h = col >> 6;
                const int di = col & 63;
                const int b0i = r0 >> 11, n0i = r0 & 2047;
                const int r1 = r0 + 8;
                const int b1i = r1 >> 11, n1i = r1 & 2047;
                *(float2*)(out + (((size_t)(b0i * H_ + h)) * N_ + n0i) * DH_ + di) = v0;
                *(float2*)(out + (((size_t)(b1i * H_ + h)) * N_ + n1i) * DH_ + di) = v1;
            } else {
                *(float2*)(out + (size_t)r0 * D_ + col) = v0;
                *(float2*)(out + (size_t)(r0 + 8) * D_ + col) = v1;
            }
        }
    }
}

__global__ __launch_bounds__(256, 2)
void proj_qkv_mma(const float* __restrict__ xq, const float* __restrict__ xk,
                  const float* __restrict__ xv,
                  const float* __restrict__ Wq, const float* __restrict__ bq,
                  const float* __restrict__ Wk, const float* __restrict__ bk,
                  const float* __restrict__ Wv, const float* __restrict__ bv)
{
    int z = blockIdx.z;
    const float* A = (z == 0) ? xq : (z == 1) ? xk : xv;
    const float* W = (z == 0) ? Wq : (z == 1) ? Wk : Wv;
    const float* b = (z == 0) ? bq : (z == 1) ? bk : bv;
    float* out = (z == 0) ? g_Q : (z == 1) ? g_K : g_V;
    gemm_mma_body<true, true>(A, W, b, out);
}

__global__ __launch_bounds__(256, 2)
void proj_out_mma(const float* __restrict__ Wo, float* __restrict__ out)
{
    gemm_mma_body<false, false>(g_X, Wo, nullptr, out);
}

// ===========================================================================
// Tensor-core flash attention (tf32 mma.sync), causal, dh=64.
// CTA: 256 threads (8 warps), 128-query tile; warp w owns rows w*16..w*16+15.
// K/V staging amortized over 2x more Q rows than the 64q version.
// Warp-uniform skip of fully-masked diagonal warp-tiles.
// ===========================================================================
#define QSTR 68
#define VSTR 72
#define FL_SMEM ((128 * QSTR + 64 * QSTR + 64 * VSTR) * 4)

__global__ __launch_bounds__(256, 2) void flash_mma_kernel()
{
    extern __shared__ uint32_t fsm[];
    uint32_t* Qs = fsm;                  // [128][QSTR]
    uint32_t* Ks = Qs + 128 * QSTR;      // [64][QSTR]
    uint32_t* Vs = Ks + 64 * QSTR;       // [64][VSTR]

    const int tid  = threadIdx.x;
    const int wq   = tid >> 5;           // 0..7
    const int lane = tid & 31;
    const int g    = lane >> 2;
    const int tig  = lane & 3;
    const int qt   = gridDim.x - 1 - blockIdx.x;   // long CTAs first
    const int bh   = blockIdx.y;
    const int qi0  = qt * 128;

    const float* Qg = g_Q + (size_t)bh * N_ * DH_;
    const float* Kg = g_K + (size_t)bh * N_ * DH_;
    const float* Vg = g_V + (size_t)bh * N_ * DH_;

    const float qscale = 0.125f * 1.44269504088896340736f; // dh^-0.5 * log2(e)

    // Stage Q tile: 128 rows x 16 float4 = 2048 slots / 256 thr = 8 iters
#pragma unroll
    for (int u = 0; u < 8; u++) {
        int f  = tid + 256 * u;
        int r  = f >> 4;
        int dv = f & 15;
        float4 v = *(const float4*)(Qg + (size_t)(qi0 + r) * DH_ + dv * 4);
        uint4 t;
        t.x = f2tf32(v.x * qscale); t.y = f2tf32(v.y * qscale);
        t.z = f2tf32(v.z * qscale); t.w = f2tf32(v.w * qscale);
        *(uint4*)&Qs[r * QSTR + dv * 4] = t;
    }

    float m0r = -1e30f, m1r = -1e30f;
    float l0r = 0.f, l1r = 0.f;
    float O[8][4];
#pragma unroll
    for (int j = 0; j < 8; j++)
#pragma unroll
        for (int e = 0; e < 4; e++) O[j][e] = 0.f;

    const int row0 = qi0 + wq * 16 + g;
    const int row1 = row0 + 8;
    const int wrow_min = qi0 + wq * 16;
    const int wrow_max = wrow_min + 15;

    const int NKT = 2 * qt + 2;          // k-tiles: cover rows up to qi0+127

    for (int kt2 = 0; kt2 < NKT; kt2++) {
        const int kj0 = kt2 * 64;
        __syncthreads();

        // Stage K and V: 64 rows x 16 float4 = 1024 slots / 256 thr = 4 iters
#pragma unroll
        for (int u = 0; u < 4; u++) {
            int f  = tid + 256 * u;
            int r  = f >> 4;
            int dv = f & 15;
            float4 kv = *(const float4*)(Kg + (size_t)(kj0 + r) * DH_ + dv * 4);
            uint4 kt_;
            kt_.x = f2tf32(kv.x); kt_.y = f2tf32(kv.y);
            kt_.z = f2tf32(kv.z); kt_.w = f2tf32(kv.w);
            *(uint4*)&Ks[r * QSTR + dv * 4] = kt_;
            float4 vv = *(const float4*)(Vg + (size_t)(kj0 + r) * DH_ + dv * 4);
            uint4 vt;
            vt.x = f2tf32(vv.x); vt.y = f2tf32(vv.y);
            vt.z = f2tf32(vv.z); vt.w = f2tf32(vv.w);
            *(uint4*)&Vs[r * VSTR + dv * 4] = vt;
        }
        __syncthreads();

        // Warp-uniform skip: all rows of this warp are strictly above kj0
        if (kj0 > wrow_max) continue;

        // ---- S = Qs @ Ks^T ----
        float S[8][4];
#pragma unroll
        for (int j = 0; j < 8; j++)
#pragma unroll
            for (int e = 0; e < 4; e++) S[j][e] = 0.f;

#pragma unroll
        for (int kb = 0; kb < 8; kb++) {
            const int ar = (wq * 16 + g) * QSTR + kb * 8 + tig;
            uint32_t a0 = Qs[ar];
            uint32_t a1 = Qs[ar + 8 * QSTR];
            uint32_t a2 = Qs[ar + 4];
            uint32_t a3 = Qs[ar + 8 * QSTR + 4];
#pragma unroll
            for (int j = 0; j < 8; j++) {
                const int br = (j * 8 + g) * QSTR + kb * 8 + tig;
                uint32_t b0 = Ks[br];
                uint32_t b1 = Ks[br + 4];
                mma_tf32_16x8x8(S[j][0], S[j][1], S[j][2], S[j][3],
                                a0, a1, a2, a3, b0, b1);
            }
        }

        // ---- causal mask (diagonal region only) ----
        if (kj0 + 63 > wrow_min) {
#pragma unroll
            for (int j = 0; j < 8; j++) {
                int c = kj0 + j * 8 + tig * 2;
                if (c     > row0) S[j][0] = -1e30f;
                if (c + 1 > row0) S[j][1] = -1e30f;
                if (c     > row1) S[j][2] = -1e30f;
                if (c + 1 > row1) S[j][3] = -1e30f;
            }
        }

        // ---- online softmax (exp2 domain) ----
        float rmax0 = -1e30f, rmax1 = -1e30f;
#pragma unroll
        for (int j = 0; j < 8; j++) {
            rmax0 = fmaxf(rmax0, fmaxf(S[j][0], S[j][1]));
            rmax1 = fmaxf(rmax1, fmaxf(S[j][2], S[j][3]));
        }
        rmax0 = fmaxf(rmax0, __shfl_xor_sync(0xffffffffu, rmax0, 1));
        rmax0 = fmaxf(rmax0, __shfl_xor_sync(0xffffffffu, rmax0, 2));
        rmax1 = fmaxf(rmax1, __shfl_xor_sync(0xffffffffu, rmax1, 1));
        rmax1 = fmaxf(rmax1, __shfl_xor_sync(0xffffffffu, rmax1, 2));

        float mn0 = fmaxf(m0r, rmax0);
        float mn1 = fmaxf(m1r, rmax1);
        float al0 = ex2f(m0r - mn0);
        float al1 = ex2f(m1r - mn1);
        m0r = mn0; m1r = mn1;

        float sum0 = 0.f, sum1 = 0.f;
        uint32_t P[8][4];
#pragma unroll
        for (int j = 0; j < 8; j++) {
            float p0 = ex2f(S[j][0] - mn0);
            float p1 = ex2f(S[j][1] - mn0);
            float p2 = ex2f(S[j][2] - mn1);
            float p3 = ex2f(S[j][3] - mn1);
            sum0 += p0 + p1;
            sum1 += p2 + p3;
            P[j][0] = f2tf32(p0); P[j][1] = f2tf32(p1);
            P[j][2] = f2tf32(p2); P[j][3] = f2tf32(p3);
        }
        sum0 += __shfl_xor_sync(0xffffffffu, sum0, 1);
        sum0 += __shfl_xor_sync(0xffffffffu, sum0, 2);
        sum1 += __shfl_xor_sync(0xffffffffu, sum1, 1);
        sum1 += __shfl_xor_sync(0xffffffffu, sum1, 2);
        l0r = l0r * al0 + sum0;
        l1r = l1r * al1 + sum1;

#pragma unroll
        for (int j = 0; j < 8; j++) {
            O[j][0] *= al0; O[j][1] *= al0;
            O[j][2] *= al1; O[j][3] *= al1;
        }

        // ---- O += P @ V (P reshaped via quad shuffles) ----
        const int srcA = (lane & ~3) | (tig >> 1);
        const int srcB = srcA + 2;
        const bool oddc = (tig & 1);
#pragma unroll
        for (int kb = 0; kb < 8; kb++) {
            uint32_t v0 = __shfl_sync(0xffffffffu, P[kb][0], srcA);
            uint32_t v1 = __shfl_sync(0xffffffffu, P[kb][1], srcA);
            uint32_t a0 = oddc ? v1 : v0;
            uint32_t w0 = __shfl_sync(0xffffffffu, P[kb][0], srcB);
            uint32_t w1 = __shfl_sync(0xffffffffu, P[kb][1], srcB);
            uint32_t a2 = oddc ? w1 : w0;
            uint32_t x0 = __shfl_sync(0xffffffffu, P[kb][2], srcA);
            uint32_t x1 = __shfl_sync(0xffffffffu, P[kb][3], srcA);
            uint32_t a1 = oddc ? x1 : x0;
            uint32_t y0 = __shfl_sync(0xffffffffu, P[kb][2], srcB);
            uint32_t y1 = __shfl_sync(0xffffffffu, P[kb][3], srcB);
            uint32_t a3 = oddc ? y1 : y0;
#pragma unroll
            for (int j = 0; j < 8; j++) {
                uint32_t b0 = Vs[(kb * 8 + tig) * VSTR + j * 8 + g];
                uint32_t b1 = Vs[(kb * 8 + tig + 4) * VSTR + j * 8 + g];
                mma_tf32_16x8x8(O[j][0], O[j][1], O[j][2], O[j][3],
                                a0, a1, a2, a3, b0, b1);
            }
        }
    }

    // Epilogue: O /= l; write to g_X[b][n][h*64 + e]
    const int b = bh >> 4;
    const int h = bh & 15;
    const float il0 = 1.f / l0r;
    const float il1 = 1.f / l1r;
    float* X0 = g_X + ((size_t)b * N_ + row0) * D_ + h * DH_;
    float* X1 = g_X + ((size_t)b * N_ + row1) * D_ + h * DH_;
#pragma unroll
    for (int j = 0; j < 8; j++) {
        int e = j * 8 + tig * 2;
        *(float2*)(X0 + e) = make_float2(O[j][0] * il0, O[j][1] * il0);
        *(float2*)(X1 + e) = make_float2(O[j][2] * il1, O[j][3] * il1);
    }
}

// ---------------------------------------------------------------------------
extern "C" void kernel_launch(void* const* d_in, const int* in_sizes, int n_in,
                              void* d_out, int out_size)
{
    const float* q  = (const float*)d_in[0];
    const float* k  = (const float*)d_in[1];
    const float* v  = (const float*)d_in[2];
    const float* Wq = (const float*)d_in[3];
    const float* bq = (const float*)d_in[4];
    const float* Wk = (const float*)d_in[5];
    const float* bk = (const float*)d_in[6];
    const float* Wv = (const float*)d_in[7];
    const float* bv = (const float*)d_in[8];
    const float* Wo = (const float*)d_in[9];
    float* out = (float*)d_out;

    cudaFuncSetAttribute(proj_qkv_mma, cudaFuncAttributeMaxDynamicSharedMemorySize, GEMM_SMEM);
    cudaFuncSetAttribute(proj_out_mma, cudaFuncAttributeMaxDynamicSharedMemorySize, GEMM_SMEM);
    cudaFuncSetAttribute(flash_mma_kernel, cudaFuncAttributeMaxDynamicSharedMemorySize, FL_SMEM);

    // QKV projections: M=8192 -> 64 row-tiles, N=1024 -> 8 col-tiles, z = q/k/v
    dim3 gp(8, 64, 3);
    proj_qkv_mma<<<gp, 256, GEMM_SMEM>>>(q, k, v, Wq, bq, Wk, bk, Wv, bv);

    // Flash attention: 16 q-tiles (128 rows) x 64 (b,h) pairs
    dim3 gf(N_ / 128, B_ * H_);
    flash_mma_kernel<<<gf, 256, FL_SMEM>>>();

    // Output projection
    dim3 go(8, 64, 1);
    proj_out_mma<<<go, 256, GEMM_SMEM>>>(Wo, out);
}

// round 8
// speedup vs baseline: 1.0156x; 1.0156x over previous
#include <cuda_runtime.h>
#include <cstdint>
#include <math.h>

#define B_  4
#define N_  2048
#define D_  1024
#define H_  16
#define DH_ 64

// Scratch: projected Q/K/V in [B*H][N][dh] layout, attention output X in [B*N][D]
__device__ float g_Q[B_ * H_ * N_ * DH_];
__device__ float g_K[B_ * H_ * N_ * DH_];
__device__ float g_V[B_ * H_ * N_ * DH_];
__device__ float g_X[B_ * N_ * D_];

__device__ __forceinline__ uint32_t f2tf32(float x) {
    uint32_t r;
    asm("cvt.rna.tf32.f32 %0, %1;" : "=r"(r) : "f"(x));
    return r;
}
__device__ __forceinline__ float ex2f(float x) {
    float y;
    asm("ex2.approx.ftz.f32 %0, %1;" : "=f"(y) : "f"(x));
    return y;
}

__device__ __forceinline__ void mma_tf32_16x8x8(
    float& c0, float& c1, float& c2, float& c3,
    uint32_t a0, uint32_t a1, uint32_t a2, uint32_t a3,
    uint32_t b0, uint32_t b1)
{
    asm volatile(
        "mma.sync.aligned.m16n8k8.row.col.f32.tf32.tf32.f32 "
        "{%0,%1,%2,%3}, {%4,%5,%6,%7}, {%8,%9}, {%0,%1,%2,%3};"
        : "+f"(c0), "+f"(c1), "+f"(c2), "+f"(c3)
        : "r"(a0), "r"(a1), "r"(a2), "r"(a3), "r"(b0), "r"(b1));
}

// ===========================================================================
// tf32 mma.sync GEMM: C[M,1024] = A[M,1024] @ W^T (+bias), W row-major [N][K].
// CTA tile 128x128, k-tile 32, 8 warps (4m x 2n), warp tile 32x64.
// Smem: padded row-major [row][KSTR=36], R4-proven conflict-free layout.
// 2-stage ring + register prefetch: LDG(t+1)->regs, compute(t), STS(t+1), sync.
// Producer-side cvt.rna -> tf32 (inner loop has NO cvt, NO extra ALU).
// ===========================================================================
#define KSTR 36
#define MATF (128 * KSTR)                 // floats per matrix tile (padded)
#define STGF (2 * MATF)                   // A + B per stage
#define GEMM_SMEM (2 * STGF * 4)          // 2 stages = 73728 B

template <bool OUT_HEADS, bool HAS_BIAS>
__device__ __forceinline__ void gemm_mma_body(
    const float* __restrict__ A, const float* __restrict__ W,
    const float* __restrict__ bias, float* __restrict__ out)
{
    extern __shared__ uint32_t gsm[];

    const int tid  = threadIdx.x;
    const int wid  = tid >> 5;
    const int lane = tid & 31;
    const int g    = lane >> 2;
    const int tig  = lane & 3;
    const int wm   = wid & 3;
    const int wn   = wid >> 2;
    const int m0   = blockIdx.y * 128;
    const int n0   = blockIdx.x * 128;

    const int prow = tid >> 1;               // producer row 0..127
    const int pq   = (tid & 1) * 4;          // producer float4-chunk base {0,4}

    float c[2][8][4];
#pragma unroll
    for (int t = 0; t < 2; t++)
#pragma unroll
        for (int j = 0; j < 8; j++)
#pragma unroll
            for (int e = 0; e < 4; e++) c[t][j][e] = 0.f;

    const float* Ath = A + (size_t)(m0 + prow) * D_ + pq * 4;
    const float* Wth = W + (size_t)(n0 + prow) * D_ + pq * 4;
    const int sts_off = prow * KSTR + pq * 4;   // constant per thread

    uint4 pa[4], pw[4];

    // load + convert tile 0
#pragma unroll
    for (int j = 0; j < 4; j++) {
        float4 av = __ldg((const float4*)(Ath + j * 4));
        pa[j].x = f2tf32(av.x); pa[j].y = f2tf32(av.y);
        pa[j].z = f2tf32(av.z); pa[j].w = f2tf32(av.w);
        float4 wv = __ldg((const float4*)(Wth + j * 4));
        pw[j].x = f2tf32(wv.x); pw[j].y = f2tf32(wv.y);
        pw[j].z = f2tf32(wv.z); pw[j].w = f2tf32(wv.w);
    }
    {
        uint32_t* As = gsm;
        uint32_t* Bs = gsm + MATF;
#pragma unroll
        for (int j = 0; j < 4; j++) {
            *(uint4*)(As + sts_off + j * 4) = pa[j];
            *(uint4*)(Bs + sts_off + j * 4) = pw[j];
        }
    }
    __syncthreads();

    const int NK = D_ / 32;
    for (int kt = 0; kt < NK; kt++) {
        // prefetch tile kt+1 into registers (hidden under compute)
        if (kt + 1 < NK) {
            const float* Ag = Ath + (kt + 1) * 32;
            const float* Wg = Wth + (kt + 1) * 32;
#pragma unroll
            for (int j = 0; j < 4; j++) {
                float4 av = __ldg((const float4*)(Ag + j * 4));
                pa[j].x = f2tf32(av.x); pa[j].y = f2tf32(av.y);
                pa[j].z = f2tf32(av.z); pa[j].w = f2tf32(av.w);
                float4 wv = __ldg((const float4*)(Wg + j * 4));
                pw[j].x = f2tf32(wv.x); pw[j].y = f2tf32(wv.y);
                pw[j].z = f2tf32(wv.z); pw[j].w = f2tf32(wv.w);
            }
        }

        // compute from current stage (R4 inner loop, unmodified)
        const uint32_t* As = gsm + (kt & 1) * STGF;
        const uint32_t* Bs = As + MATF;

#pragma unroll
        for (int kk = 0; kk < 32; kk += 8) {
            uint32_t a[2][4];
#pragma unroll
            for (int t = 0; t < 2; t++) {
                int r = (wm * 32 + t * 16 + g) * KSTR + kk + tig;
                a[t][0] = As[r];
                a[t][1] = As[r + 8 * KSTR];
                a[t][2] = As[r + 4];
                a[t][3] = As[r + 8 * KSTR + 4];
            }
            uint32_t b[8][2];
#pragma unroll
            for (int j = 0; j < 8; j++) {
                int r = (wn * 64 + j * 8 + g) * KSTR + kk + tig;
                b[j][0] = Bs[r];
                b[j][1] = Bs[r + 4];
            }
#pragma unroll
            for (int t = 0; t < 2; t++)
#pragma unroll
                for (int j = 0; j < 8; j++)
                    mma_tf32_16x8x8(c[t][j][0], c[t][j][1], c[t][j][2], c[t][j][3],
                                    a[t][0], a[t][1], a[t][2], a[t][3],
                                    b[j][0], b[j][1]);
        }

        // store prefetched tile into the other stage
        if (kt + 1 < NK) {
            uint32_t* Ad = gsm + ((kt + 1) & 1) * STGF;
            uint32_t* Bd = Ad + MATF;
#pragma unroll
            for (int j = 0; j < 4; j++) {
                *(uint4*)(Ad + sts_off + j * 4) = pa[j];
                *(uint4*)(Bd + sts_off + j * 4) = pw[j];
            }
        }
        __syncthreads();
    }

    // Epilogue
#pragma unroll
    for (int t = 0; t < 2; t++) {
        const int r0 = m0 + wm * 32 + t * 16 + g;
#pragma unroll
        for (int j = 0; j < 8; j++) {
            const int col = n0 + wn * 64 + j * 8 + tig * 2;
            float2 v0 = make_float2(c[t][j][0], c[t][j][1]);
            float2 v1 = make_float2(c[t][j][2], c[t][j][3]);
            if (HAS_BIAS) {
                float2 bv = *(const float2*)(bias + col);
                v0.x += bv.x; v0.y += bv.y;
                v1.x += bv.x; v1.y += bv.y;
            }
            if (OUT_HEADS) {
                const int h = col >> 6;
                const int di = col & 63;
                const int b0i = r0 >> 11, n0i = r0 & 2047;
                const int r1 = r0 + 8;
                const int b1i = r1 >> 11, n1i = r1 & 2047;
                *(float2*)(out + (((size_t)(b0i * H_ + h)) * N_ + n0i) * DH_ + di) = v0;
                *(float2*)(out + (((size_t)(b1i * H_ + h)) * N_ + n1i) * DH_ + di) = v1;
            } else {
                *(float2*)(out + (size_t)r0 * D_ + col) = v0;
                *(float2*)(out + (size_t)(r0 + 8) * D_ + col) = v1;
            }
        }
    }
}

__global__ __launch_bounds__(256, 2)
void proj_qkv_mma(const float* __restrict__ xq, const float* __restrict__ xk,
                  const float* __restrict__ xv,
                  const float* __restrict__ Wq, const float* __restrict__ bq,
                  const float* __restrict__ Wk, const float* __restrict__ bk,
                  const float* __restrict__ Wv, const float* __restrict__ bv)
{
    int z = blockIdx.z;
    const float* A = (z == 0) ? xq : (z == 1) ? xk : xv;
    const float* W = (z == 0) ? Wq : (z == 1) ? Wk : Wv;
    const float* b = (z == 0) ? bq : (z == 1) ? bk : bv;
    float* out = (z == 0) ? g_Q : (z == 1) ? g_K : g_V;
    gemm_mma_body<true, true>(A, W, b, out);
}

__global__ __launch_bounds__(256, 2)
void proj_out_mma(const float* __restrict__ Wo, float* __restrict__ out)
{
    gemm_mma_body<false, false>(g_X, Wo, nullptr, out);
}

// ===========================================================================
// Tensor-core flash attention (tf32 mma.sync), causal, dh=64.
// CTA: 128 threads (4 warps). 64-query tile (known-330us R4/R6 version).
// Reversed q-tile launch order (long CTAs first).
// ===========================================================================
#define QSTR 68
#define VSTR 72
#define FL_SMEM ((64 * QSTR * 2 + 64 * VSTR) * 4)

__global__ __launch_bounds__(128, 4) void flash_mma_kernel()
{
    extern __shared__ uint32_t fsm[];
    uint32_t* Qs = fsm;                 // [64][QSTR]
    uint32_t* Ks = Qs + 64 * QSTR;      // [64][QSTR]
    uint32_t* Vs = Ks + 64 * QSTR;      // [64][VSTR]

    const int tid  = threadIdx.x;
    const int wq   = tid >> 5;
    const int lane = tid & 31;
    const int g    = lane >> 2;
    const int tig  = lane & 3;
    const int qt   = gridDim.x - 1 - blockIdx.x;
    const int bh   = blockIdx.y;
    const int qi0  = qt * 64;

    const float* Qg = g_Q + (size_t)bh * N_ * DH_;
    const float* Kg = g_K + (size_t)bh * N_ * DH_;
    const float* Vg = g_V + (size_t)bh * N_ * DH_;

    const float qscale = 0.125f * 1.44269504088896340736f;

#pragma unroll
    for (int u = 0; u < 8; u++) {
        int f  = tid + 128 * u;
        int r  = f >> 4;
        int dv = f & 15;
        float4 v = *(const float4*)(Qg + (size_t)(qi0 + r) * DH_ + dv * 4);
        uint4 t;
        t.x = f2tf32(v.x * qscale); t.y = f2tf32(v.y * qscale);
        t.z = f2tf32(v.z * qscale); t.w = f2tf32(v.w * qscale);
        *(uint4*)&Qs[r * QSTR + dv * 4] = t;
    }

    float m0r = -1e30f, m1r = -1e30f;
    float l0r = 0.f, l1r = 0.f;
    float O[8][4];
#pragma unroll
    for (int j = 0; j < 8; j++)
#pragma unroll
        for (int e = 0; e < 4; e++) O[j][e] = 0.f;

    const int row0 = qi0 + wq * 16 + g;
    const int row1 = row0 + 8;

    for (int kt2 = 0; kt2 <= qt; kt2++) {
        const int kj0 = kt2 * 64;
        __syncthreads();

#pragma unroll
        for (int u = 0; u < 8; u++) {
            int f  = tid + 128 * u;
            int r  = f >> 4;
            int dv = f & 15;
            float4 kv = *(const float4*)(Kg + (size_t)(kj0 + r) * DH_ + dv * 4);
            uint4 kt_;
            kt_.x = f2tf32(kv.x); kt_.y = f2tf32(kv.y);
            kt_.z = f2tf32(kv.z); kt_.w = f2tf32(kv.w);
            *(uint4*)&Ks[r * QSTR + dv * 4] = kt_;
            float4 vv = *(const float4*)(Vg + (size_t)(kj0 + r) * DH_ + dv * 4);
            uint4 vt;
            vt.x = f2tf32(vv.x); vt.y = f2tf32(vv.y);
            vt.z = f2tf32(vv.z); vt.w = f2tf32(vv.w);
            *(uint4*)&Vs[r * VSTR + dv * 4] = vt;
        }
        __syncthreads();

        float S[8][4];
#pragma unroll
        for (int j = 0; j < 8; j++)
#pragma unroll
            for (int e = 0; e < 4; e++) S[j][e] = 0.f;

#pragma unroll
        for (int kb = 0; kb < 8; kb++) {
            const int ar = (wq * 16 + g) * QSTR + kb * 8 + tig;
            uint32_t a0 = Qs[ar];
            uint32_t a1 = Qs[ar + 8 * QSTR];
            uint32_t a2 = Qs[ar + 4];
            uint32_t a3 = Qs[ar + 8 * QSTR + 4];
#pragma unroll
            for (int j = 0; j < 8; j++) {
                const int br = (j * 8 + g) * QSTR + kb * 8 + tig;
                uint32_t b0 = Ks[br];
                uint32_t b1 = Ks[br + 4];
                mma_tf32_16x8x8(S[j][0], S[j][1], S[j][2], S[j][3],
                                a0, a1, a2, a3, b0, b1);
            }
        }

        if (kt2 == qt) {
#pragma unroll
            for (int j = 0; j < 8; j++) {
                int c = kj0 + j * 8 + tig * 2;
                if (c     > row0) S[j][0] = -1e30f;
                if (c + 1 > row0) S[j][1] = -1e30f;
                if (c     > row1) S[j][2] = -1e30f;
                if (c + 1 > row1) S[j][3] = -1e30f;
            }
        }

        float rmax0 = -1e30f, rmax1 = -1e30f;
#pragma unroll
        for (int j = 0; j < 8; j++) {
            rmax0 = fmaxf(rmax0, fmaxf(S[j][0], S[j][1]));
            rmax1 = fmaxf(rmax1, fmaxf(S[j][2], S[j][3]));
        }
        rmax0 = fmaxf(rmax0, __shfl_xor_sync(0xffffffffu, rmax0, 1));
        rmax0 = fmaxf(rmax0, __shfl_xor_sync(0xffffffffu, rmax0, 2));
        rmax1 = fmaxf(rmax1, __shfl_xor_sync(0xffffffffu, rmax1, 1));
        rmax1 = fmaxf(rmax1, __shfl_xor_sync(0xffffffffu, rmax1, 2));

        float mn0 = fmaxf(m0r, rmax0);
        float mn1 = fmaxf(m1r, rmax1);
        float al0 = ex2f(m0r - mn0);
        float al1 = ex2f(m1r - mn1);
        m0r = mn0; m1r = mn1;

        float sum0 = 0.f, sum1 = 0.f;
        uint32_t P[8][4];
#pragma unroll
        for (int j = 0; j < 8; j++) {
            float p0 = ex2f(S[j][0] - mn0);
            float p1 = ex2f(S[j][1] - mn0);
            float p2 = ex2f(S[j][2] - mn1);
            float p3 = ex2f(S[j][3] - mn1);
            sum0 += p0 + p1;
            sum1 += p2 + p3;
            P[j][0] = f2tf32(p0); P[j][1] = f2tf32(p1);
            P[j][2] = f2tf32(p2); P[j][3] = f2tf32(p3);
        }
        sum0 += __shfl_xor_sync(0xffffffffu, sum0, 1);
        sum0 += __shfl_xor_sync(0xffffffffu, sum0, 2);
        sum1 += __shfl_xor_sync(0xffffffffu, sum1, 1);
        sum1 += __shfl_xor_sync(0xffffffffu, sum1, 2);
        l0r = l0r * al0 + sum0;
        l1r = l1r * al1 + sum1;

#pragma unroll
        for (int j = 0; j < 8; j++) {
            O[j][0] *= al0; O[j][1] *= al0;
            O[j][2] *= al1; O[j][3] *= al1;
        }

        const int srcA = (lane & ~3) | (tig >> 1);
        const int srcB = srcA + 2;
        const bool oddc = (tig & 1);
#pragma unroll
        for (int kb = 0; kb < 8; kb++) {
            uint32_t v0 = __shfl_sync(0xffffffffu, P[kb][0], srcA);
            uint32_t v1 = __shfl_sync(0xffffffffu, P[kb][1], srcA);
            uint32_t a0 = oddc ? v1 : v0;
            uint32_t w0 = __shfl_sync(0xffffffffu, P[kb][0], srcB);
            uint32_t w1 = __shfl_sync(0xffffffffu, P[kb][1], srcB);
            uint32_t a2 = oddc ? w1 : w0;
            uint32_t x0 = __shfl_sync(0xffffffffu, P[kb][2], srcA);
            uint32_t x1 = __shfl_sync(0xffffffffu, P[kb][3], srcA);
            uint32_t a1 = oddc ? x1 : x0;
            uint32_t y0 = __shfl_sync(0xffffffffu, P[kb][2], srcB);
            uint32_t y1 = __shfl_sync(0xffffffffu, P[kb][3], srcB);
            uint32_t a3 = oddc ? y1 : y0;
#pragma unroll
            for (int j = 0; j < 8; j++) {
                uint32_t b0 = Vs[(kb * 8 + tig) * VSTR + j * 8 + g];
                uint32_t b1 = Vs[(kb * 8 + tig + 4) * VSTR + j * 8 + g];
                mma_tf32_16x8x8(O[j][0], O[j][1], O[j][2], O[j][3],
                                a0, a1, a2, a3, b0, b1);
            }
        }
    }

    const int b = bh >> 4;
    const int h = bh & 15;
    const float il0 = 1.f / l0r;
    const float il1 = 1.f / l1r;
    float* X0 = g_X + ((size_t)b * N_ + row0) * D_ + h * DH_;
    float* X1 = g_X + ((size_t)b * N_ + row1) * D_ + h * DH_;
#pragma unroll
    for (int j = 0; j < 8; j++) {
        int e = j * 8 + tig * 2;
        *(float2*)(X0 + e) = make_float2(O[j][0] * il0, O[j][1] * il0);
        *(float2*)(X1 + e) = make_float2(O[j][2] * il1, O[j][3] * il1);
    }
}

// ---------------------------------------------------------------------------
extern "C" void kernel_launch(void* const* d_in, const int* in_sizes, int n_in,
                              void* d_out, int out_size)
{
    const float* q  = (const float*)d_in[0];
    const float* k  = (const float*)d_in[1];
    const float* v  = (const float*)d_in[2];
    const float* Wq = (const float*)d_in[3];
    const float* bq = (const float*)d_in[4];
    const float* Wk = (const float*)d_in[5];
    const float* bk = (const float*)d_in[6];
    const float* Wv = (const float*)d_in[7];
    const float* bv = (const float*)d_in[8];
    const float* Wo = (const float*)d_in[9];
    float* out = (float*)d_out;

    cudaFuncSetAttribute(proj_qkv_mma, cudaFuncAttributeMaxDynamicSharedMemorySize, GEMM_SMEM);
    cudaFuncSetAttribute(proj_out_mma, cudaFuncAttributeMaxDynamicSharedMemorySize, GEMM_SMEM);
    cudaFuncSetAttribute(flash_mma_kernel, cudaFuncAttributeMaxDynamicSharedMemorySize, FL_SMEM);

    // QKV projections: M=8192 -> 64 row-tiles, N=1024 -> 8 col-tiles, z = q/k/v
    dim3 gp(8, 64, 3);
    proj_qkv_mma<<<gp, 256, GEMM_SMEM>>>(q, k, v, Wq, bq, Wk, bk, Wv, bv);

    // Flash attention: 32 q-tiles x 64 (b,h) pairs
    dim3 gf(N_ / 64, B_ * H_);
    flash_mma_kernel<<<gf, 128, FL_SMEM>>>();

    // Output projection
    dim3 go(8, 64, 1);
    proj_out_mma<<<go, 256, GEMM_SMEM>>>(Wo, out);
}

// round 9
// speedup vs baseline: 1.2591x; 1.2397x over previous
#include <cuda_runtime.h>
#include <cstdint>
#include <math.h>

#define B_  4
#define N_  2048
#define D_  1024
#define H_  16
#define DH_ 64

// Scratch: projected Q/K/V in [B*H][N][dh] layout, attention output X in [B*N][D]
__device__ float g_Q[B_ * H_ * N_ * DH_];
__device__ float g_K[B_ * H_ * N_ * DH_];
__device__ float g_V[B_ * H_ * N_ * DH_];
__device__ float g_X[B_ * N_ * D_];

__device__ __forceinline__ uint32_t f2tf32(float x) {
    uint32_t r;
    asm("cvt.rna.tf32.f32 %0, %1;" : "=r"(r) : "f"(x));
    return r;
}
__device__ __forceinline__ float ex2f(float x) {
    float y;
    asm("ex2.approx.ftz.f32 %0, %1;" : "=f"(y) : "f"(x));
    return y;
}

__device__ __forceinline__ void mma_tf32_16x8x8(
    float& c0, float& c1, float& c2, float& c3,
    uint32_t a0, uint32_t a1, uint32_t a2, uint32_t a3,
    uint32_t b0, uint32_t b1)
{
    asm volatile(
        "mma.sync.aligned.m16n8k8.row.col.f32.tf32.tf32.f32 "
        "{%0,%1,%2,%3}, {%4,%5,%6,%7}, {%8,%9}, {%0,%1,%2,%3};"
        : "+f"(c0), "+f"(c1), "+f"(c2), "+f"(c3)
        : "r"(a0), "r"(a1), "r"(a2), "r"(a3), "r"(b0), "r"(b1));
}

// ===========================================================================
// tf32 mma.sync GEMM: C[M,1024] = A[M,1024] @ W^T (+bias), W row-major [N][K].
// CTA tile 128x128, k-tile 32. 8 warps (4 m x 2 n), warp tile 32x64.
// R4 structure (static smem, LDG->cvt->STS producer, 2 syncs per k-tile)
// + double-buffered smem FRAGMENTS: k-block kb+1 loads issue before kb's MMAs.
// ===========================================================================
#define KSTR 36   // padded k stride in uint32

template <bool OUT_HEADS, bool HAS_BIAS>
__device__ __forceinline__ void gemm_mma_body(
    const float* __restrict__ A, const float* __restrict__ W,
    const float* __restrict__ bias, float* __restrict__ out)
{
    __shared__ uint32_t As[128 * KSTR];
    __shared__ uint32_t Bs[128 * KSTR];

    const int tid  = threadIdx.x;
    const int wid  = tid >> 5;
    const int lane = tid & 31;
    const int g    = lane >> 2;
    const int tig  = lane & 3;
    const int wm   = wid & 3;
    const int wn   = wid >> 2;
    const int m0   = blockIdx.y * 128;
    const int n0   = blockIdx.x * 128;

    float c[2][8][4];
#pragma unroll
    for (int t = 0; t < 2; t++)
#pragma unroll
        for (int j = 0; j < 8; j++)
#pragma unroll
            for (int e = 0; e < 4; e++) c[t][j][e] = 0.f;

    // fragment base offsets (k-block offset added per load)
    const int arow0 = (wm * 32 + g) * KSTR + tig;        // m-tile t adds t*16*KSTR
    const int brow0 = (wn * 64 + g) * KSTR + tig;        // n-tile j adds j*8*KSTR

    for (int kt = 0; kt < D_; kt += 32) {
        // Producer: load 128x32 tiles of A and W, convert to tf32, store padded.
#pragma unroll
        for (int u = 0; u < 4; u++) {
            int f   = tid + 256 * u;
            int row = f >> 3;
            int q   = f & 7;
            float4 av = __ldg((const float4*)(A + (size_t)(m0 + row) * D_ + kt + q * 4));
            uint4 at;
            at.x = f2tf32(av.x); at.y = f2tf32(av.y);
            at.z = f2tf32(av.z); at.w = f2tf32(av.w);
            *(uint4*)&As[row * KSTR + q * 4] = at;
            float4 wv = __ldg((const float4*)(W + (size_t)(n0 + row) * D_ + kt + q * 4));
            uint4 wt;
            wt.x = f2tf32(wv.x); wt.y = f2tf32(wv.y);
            wt.z = f2tf32(wv.z); wt.w = f2tf32(wv.w);
            *(uint4*)&Bs[row * KSTR + q * 4] = wt;
        }
        __syncthreads();

        // Consumer: double-buffered fragments across the 4 k-blocks.
        uint32_t a[2][2][4];   // [buf][m-tile][elem]
        uint32_t b[2][8][2];   // [buf][n-tile][elem]

        // preload k-block 0 into buf 0
#pragma unroll
        for (int t = 0; t < 2; t++) {
            int r = arow0 + t * 16 * KSTR;           // kk = 0
            a[0][t][0] = As[r];
            a[0][t][1] = As[r + 8 * KSTR];
            a[0][t][2] = As[r + 4];
            a[0][t][3] = As[r + 8 * KSTR + 4];
        }
#pragma unroll
        for (int j = 0; j < 8; j++) {
            int r = brow0 + j * 8 * KSTR;
            b[0][j][0] = Bs[r];
            b[0][j][1] = Bs[r + 4];
        }

#pragma unroll
        for (int kb = 0; kb < 4; kb++) {
            const int cur = kb & 1;
            const int nxt = cur ^ 1;
            if (kb < 3) {
                const int kk = (kb + 1) * 8;
#pragma unroll
                for (int t = 0; t < 2; t++) {
                    int r = arow0 + t * 16 * KSTR + kk;
                    a[nxt][t][0] = As[r];
                    a[nxt][t][1] = As[r + 8 * KSTR];
                    a[nxt][t][2] = As[r + 4];
                    a[nxt][t][3] = As[r + 8 * KSTR + 4];
                }
#pragma unroll
                for (int j = 0; j < 8; j++) {
                    int r = brow0 + j * 8 * KSTR + kk;
                    b[nxt][j][0] = Bs[r];
                    b[nxt][j][1] = Bs[r + 4];
                }
            }
#pragma unroll
            for (int t = 0; t < 2; t++)
#pragma unroll
                for (int j = 0; j < 8; j++)
                    mma_tf32_16x8x8(c[t][j][0], c[t][j][1], c[t][j][2], c[t][j][3],
                                    a[cur][t][0], a[cur][t][1], a[cur][t][2], a[cur][t][3],
                                    b[cur][j][0], b[cur][j][1]);
        }
        __syncthreads();
    }

    // Epilogue (R4 verbatim)
#pragma unroll
    for (int t = 0; t < 2; t++) {
        const int r0 = m0 + wm * 32 + t * 16 + g;
#pragma unroll
        for (int j = 0; j < 8; j++) {
            const int col = n0 + wn * 64 + j * 8 + tig * 2;
            float2 v0 = make_float2(c[t][j][0], c[t][j][1]);
            float2 v1 = make_float2(c[t][j][2], c[t][j][3]);
            if (HAS_BIAS) {
                float2 bv = *(const float2*)(bias + col);
                v0.x += bv.x; v0.y += bv.y;
                v1.x += bv.x; v1.y += bv.y;
            }
            if (OUT_HEADS) {
                const int h = col >> 6;
                const int di = col & 63;
                const int b0i = r0 >> 11, n0i = r0 & 2047;
                const int r1 = r0 + 8;
                const int b1i = r1 >> 11, n1i = r1 & 2047;
                *(float2*)(out + (((size_t)(b0i * H_ + h)) * N_ + n0i) * DH_ + di) = v0;
                *(float2*)(out + (((size_t)(b1i * H_ + h)) * N_ + n1i) * DH_ + di) = v1;
            } else {
                *(float2*)(out + (size_t)r0 * D_ + col) = v0;
                *(float2*)(out + (size_t)(r0 + 8) * D_ + col) = v1;
            }
        }
    }
}

__global__ __launch_bounds__(256, 2)
void proj_qkv_mma(const float* __restrict__ xq, const float* __restrict__ xk,
                  const float* __restrict__ xv,
                  const float* __restrict__ Wq, const float* __restrict__ bq,
                  const float* __restrict__ Wk, const float* __restrict__ bk,
                  const float* __restrict__ Wv, const float* __restrict__ bv)
{
    int z = blockIdx.z;
    const float* A = (z == 0) ? xq : (z == 1) ? xk : xv;
    const float* W = (z == 0) ? Wq : (z == 1) ? Wk : Wv;
    const float* b = (z == 0) ? bq : (z == 1) ? bk : bv;
    float* out = (z == 0) ? g_Q : (z == 1) ? g_K : g_V;
    gemm_mma_body<true, true>(A, W, b, out);
}

__global__ __launch_bounds__(256, 2)
void proj_out_mma(const float* __restrict__ Wo, float* __restrict__ out)
{
    gemm_mma_body<false, false>(g_X, Wo, nullptr, out);
}

// ===========================================================================
// Tensor-core flash attention (tf32 mma.sync), causal, dh=64.
// CTA: 128 threads (4 warps). 64-query tile (proven 330us version).
// Reversed q-tile launch order (long CTAs first).
// ===========================================================================
#define QSTR 68
#define VSTR 72
#define FL_SMEM ((64 * QSTR * 2 + 64 * VSTR) * 4)

__global__ __launch_bounds__(128, 4) void flash_mma_kernel()
{
    extern __shared__ uint32_t fsm[];
    uint32_t* Qs = fsm;                 // [64][QSTR]
    uint32_t* Ks = Qs + 64 * QSTR;      // [64][QSTR]
    uint32_t* Vs = Ks + 64 * QSTR;      // [64][VSTR]

    const int tid  = threadIdx.x;
    const int wq   = tid >> 5;
    const int lane = tid & 31;
    const int g    = lane >> 2;
    const int tig  = lane & 3;
    const int qt   = gridDim.x - 1 - blockIdx.x;
    const int bh   = blockIdx.y;
    const int qi0  = qt * 64;

    const float* Qg = g_Q + (size_t)bh * N_ * DH_;
    const float* Kg = g_K + (size_t)bh * N_ * DH_;
    const float* Vg = g_V + (size_t)bh * N_ * DH_;

    const float qscale = 0.125f * 1.44269504088896340736f;

#pragma unroll
    for (int u = 0; u < 8; u++) {
        int f  = tid + 128 * u;
        int r  = f >> 4;
        int dv = f & 15;
        float4 v = *(const float4*)(Qg + (size_t)(qi0 + r) * DH_ + dv * 4);
        uint4 t;
        t.x = f2tf32(v.x * qscale); t.y = f2tf32(v.y * qscale);
        t.z = f2tf32(v.z * qscale); t.w = f2tf32(v.w * qscale);
        *(uint4*)&Qs[r * QSTR + dv * 4] = t;
    }

    float m0r = -1e30f, m1r = -1e30f;
    float l0r = 0.f, l1r = 0.f;
    float O[8][4];
#pragma unroll
    for (int j = 0; j < 8; j++)
#pragma unroll
        for (int e = 0; e < 4; e++) O[j][e] = 0.f;

    const int row0 = qi0 + wq * 16 + g;
    const int row1 = row0 + 8;

    for (int kt2 = 0; kt2 <= qt; kt2++) {
        const int kj0 = kt2 * 64;
        __syncthreads();

#pragma unroll
        for (int u = 0; u < 8; u++) {
            int f  = tid + 128 * u;
            int r  = f >> 4;
            int dv = f & 15;
            float4 kv = *(const float4*)(Kg + (size_t)(kj0 + r) * DH_ + dv * 4);
            uint4 kt_;
            kt_.x = f2tf32(kv.x); kt_.y = f2tf32(kv.y);
            kt_.z = f2tf32(kv.z); kt_.w = f2tf32(kv.w);
            *(uint4*)&Ks[r * QSTR + dv * 4] = kt_;
            float4 vv = *(const float4*)(Vg + (size_t)(kj0 + r) * DH_ + dv * 4);
            uint4 vt;
            vt.x = f2tf32(vv.x); vt.y = f2tf32(vv.y);
            vt.z = f2tf32(vv.z); vt.w = f2tf32(vv.w);
            *(uint4*)&Vs[r * VSTR + dv * 4] = vt;
        }
        __syncthreads();

        float S[8][4];
#pragma unroll
        for (int j = 0; j < 8; j++)
#pragma unroll
            for (int e = 0; e < 4; e++) S[j][e] = 0.f;

#pragma unroll
        for (int kb = 0; kb < 8; kb++) {
            const int ar = (wq * 16 + g) * QSTR + kb * 8 + tig;
            uint32_t a0 = Qs[ar];
            uint32_t a1 = Qs[ar + 8 * QSTR];
            uint32_t a2 = Qs[ar + 4];
            uint32_t a3 = Qs[ar + 8 * QSTR + 4];
#pragma unroll
            for (int j = 0; j < 8; j++) {
                const int br = (j * 8 + g) * QSTR + kb * 8 + tig;
                uint32_t b0 = Ks[br];
                uint32_t b1 = Ks[br + 4];
                mma_tf32_16x8x8(S[j][0], S[j][1], S[j][2], S[j][3],
                                a0, a1, a2, a3, b0, b1);
            }
        }

        if (kt2 == qt) {
#pragma unroll
            for (int j = 0; j < 8; j++) {
                int c = kj0 + j * 8 + tig * 2;
                if (c     > row0) S[j][0] = -1e30f;
                if (c + 1 > row0) S[j][1] = -1e30f;
                if (c     > row1) S[j][2] = -1e30f;
                if (c + 1 > row1) S[j][3] = -1e30f;
            }
        }

        float rmax0 = -1e30f, rmax1 = -1e30f;
#pragma unroll
        for (int j = 0; j < 8; j++) {
            rmax0 = fmaxf(rmax0, fmaxf(S[j][0], S[j][1]));
            rmax1 = fmaxf(rmax1, fmaxf(S[j][2], S[j][3]));
        }
        rmax0 = fmaxf(rmax0, __shfl_xor_sync(0xffffffffu, rmax0, 1));
        rmax0 = fmaxf(rmax0, __shfl_xor_sync(0xffffffffu, rmax0, 2));
        rmax1 = fmaxf(rmax1, __shfl_xor_sync(0xffffffffu, rmax1, 1));
        rmax1 = fmaxf(rmax1, __shfl_xor_sync(0xffffffffu, rmax1, 2));

        float mn0 = fmaxf(m0r, rmax0);
        float mn1 = fmaxf(m1r, rmax1);
        float al0 = ex2f(m0r - mn0);
        float al1 = ex2f(m1r - mn1);
        m0r = mn0; m1r = mn1;

        float sum0 = 0.f, sum1 = 0.f;
        uint32_t P[8][4];
#pragma unroll
        for (int j = 0; j < 8; j++) {
            float p0 = ex2f(S[j][0] - mn0);
            float p1 = ex2f(S[j][1] - mn0);
            float p2 = ex2f(S[j][2] - mn1);
            float p3 = ex2f(S[j][3] - mn1);
            sum0 += p0 + p1;
            sum1 += p2 + p3;
            P[j][0] = f2tf32(p0); P[j][1] = f2tf32(p1);
            P[j][2] = f2tf32(p2); P[j][3] = f2tf32(p3);
        }
        sum0 += __shfl_xor_sync(0xffffffffu, sum0, 1);
        sum0 += __shfl_xor_sync(0xffffffffu, sum0, 2);
        sum1 += __shfl_xor_sync(0xffffffffu, sum1, 1);
        sum1 += __shfl_xor_sync(0xffffffffu, sum1, 2);
        l0r = l0r * al0 + sum0;
        l1r = l1r * al1 + sum1;

#pragma unroll
        for (int j = 0; j < 8; j++) {
            O[j][0] *= al0; O[j][1] *= al0;
            O[j][2] *= al1; O[j][3] *= al1;
        }

        const int srcA = (lane & ~3) | (tig >> 1);
        const int srcB = srcA + 2;
        const bool oddc = (tig & 1);
#pragma unroll
        for (int kb = 0; kb < 8; kb++) {
            uint32_t v0 = __shfl_sync(0xffffffffu, P[kb][0], srcA);
            uint32_t v1 = __shfl_sync(0xffffffffu, P[kb][1], srcA);
            uint32_t a0 = oddc ? v1 : v0;
            uint32_t w0 = __shfl_sync(0xffffffffu, P[kb][0], srcB);
            uint32_t w1 = __shfl_sync(0xffffffffu, P[kb][1], srcB);
            uint32_t a2 = oddc ? w1 : w0;
            uint32_t x0 = __shfl_sync(0xffffffffu, P[kb][2], srcA);
            uint32_t x1 = __shfl_sync(0xffffffffu, P[kb][3], srcA);
            uint32_t a1 = oddc ? x1 : x0;
            uint32_t y0 = __shfl_sync(0xffffffffu, P[kb][2], srcB);
            uint32_t y1 = __shfl_sync(0xffffffffu, P[kb][3], srcB);
            uint32_t a3 = oddc ? y1 : y0;
#pragma unroll
            for (int j = 0; j < 8; j++) {
                uint32_t b0 = Vs[(kb * 8 + tig) * VSTR + j * 8 + g];
                uint32_t b1 = Vs[(kb * 8 + tig + 4) * VSTR + j * 8 + g];
                mma_tf32_16x8x8(O[j][0], O[j][1], O[j][2], O[j][3],
                                a0, a1, a2, a3, b0, b1);
            }
        }
    }

    const int b = bh >> 4;
    const int h = bh & 15;
    const float il0 = 1.f / l0r;
    const float il1 = 1.f / l1r;
    float* X0 = g_X + ((size_t)b * N_ + row0) * D_ + h * DH_;
    float* X1 = g_X + ((size_t)b * N_ + row1) * D_ + h * DH_;
#pragma unroll
    for (int j = 0; j < 8; j++) {
        int e = j * 8 + tig * 2;
        *(float2*)(X0 + e) = make_float2(O[j][0] * il0, O[j][1] * il0);
        *(float2*)(X1 + e) = make_float2(O[j][2] * il1, O[j][3] * il1);
    }
}

// ---------------------------------------------------------------------------
extern "C" void kernel_launch(void* const* d_in, const int* in_sizes, int n_in,
                              void* d_out, int out_size)
{
    const float* q  = (const float*)d_in[0];
    const float* k  = (const float*)d_in[1];
    const float* v  = (const float*)d_in[2];
    const float* Wq = (const float*)d_in[3];
    const float* bq = (const float*)d_in[4];
    const float* Wk = (const float*)d_in[5];
    const float* bk = (const float*)d_in[6];
    const float* Wv = (const float*)d_in[7];
    const float* bv = (const float*)d_in[8];
    const float* Wo = (const float*)d_in[9];
    float* out = (float*)d_out;

    cudaFuncSetAttribute(flash_mma_kernel, cudaFuncAttributeMaxDynamicSharedMemorySize,
                         FL_SMEM);

    // QKV projections: M=8192 -> 64 row-tiles, N=1024 -> 8 col-tiles, z = q/k/v
    dim3 gp(8, 64, 3);
    proj_qkv_mma<<<gp, 256>>>(q, k, v, Wq, bq, Wk, bk, Wv, bv);

    // Flash attention: 32 q-tiles x 64 (b,h) pairs
    dim3 gf(N_ / 64, B_ * H_);
    flash_mma_kernel<<<gf, 128, FL_SMEM>>>();

    // Output projection
    dim3 go(8, 64, 1);
    proj_out_mma<<<go, 256>>>(Wo, out);
}